// round 14
// baseline (speedup 1.0000x reference)
#include <cuda_runtime.h>
#include <cuda_bf16.h>
#include <cstdint>

// Problem constants
#define BSZ      256
#define TSTEPS   512
#define HID      256
#define GBGROUPS 8
#define GSLICES  16
#define NCTA     128
#define BC       32
#define NU       16
#define NG       64
#define NTHREADS 256
#define HROW     136    // hT row stride in bf16 elems (128 + 8 pad)

// Persistent scratch ---------------------------------------------------------
__device__ unsigned short g_h0[2 * BSZ * HID];   // bf16 bits
__device__ unsigned short g_h1[2 * BSZ * HID];   // bf16 bits
__device__ float g_pp[BSZ * GSLICES];
__device__ float g_losspart[GBGROUPS];
__device__ int   g_bar[GBGROUPS];

// Shared memory --------------------------------------------------------------
// Weights pre-packed in m16n8k16 B-fragment order:
//   [wn:4][c:2][j:2][ks:8][lane:32][r:2][b:2]  (bf16), 16384 elems / matrix
struct SmemLayout {
    unsigned short w0 [16384];
    unsigned short w1h[16384];
    unsigned short w1i[16384];
    unsigned short hT [2][32 * HROW];
    float gbuf[BC * NG];
    float c0s [BC * NU];
    float c1s [BC * NU];
    float predvS[BC];
    float wih0 [NG];
    float bias0[NG];
    float bias1[NG];
    float woutS[NU];
    float lossS[BC];
    float boutv;
};

__device__ __forceinline__ float tanha(float x) {
    float r;
    asm("tanh.approx.f32 %0, %1;" : "=f"(r) : "f"(x));
    return r;
}
__device__ __forceinline__ float sigf(float x) {
    return 0.5f * tanha(0.5f * x) + 0.5f;
}

__device__ __forceinline__ void bar_arrive(int g) {
    __threadfence();
    __syncthreads();
    if (threadIdx.x == 0) atomicAdd(&g_bar[g], 1);
}
__device__ __forceinline__ void bar_wait(int g, int target) {
    if (threadIdx.x == 0) {
        while (((volatile int*)g_bar)[g] < target) { __nanosleep(32); }
    }
    __syncthreads();
}

// LDG 32x128 bf16 chunk into registers (8 warps, 4 rows/warp, 2 rows/iter)
__device__ __forceinline__ void ldg_h(const unsigned short* __restrict__ src,
                                      int bbase, int w, int lane, uint4 pf[2]) {
    int half = lane >> 4, kq = lane & 15;
    #pragma unroll
    for (int it = 0; it < 2; ++it) {
        int m = w * 4 + it * 2 + half;
        pf[it] = __ldcg(reinterpret_cast<const uint4*>(src + (bbase + m) * HID) + kq);
    }
}
__device__ __forceinline__ void sts_h(unsigned short* __restrict__ buf,
                                      int w, int lane, const uint4 pf[2]) {
    int half = lane >> 4, kq = lane & 15;
    #pragma unroll
    for (int it = 0; it < 2; ++it) {
        int m = w * 4 + it * 2 + half;
        *reinterpret_cast<uint4*>(buf + m * HROW + kq * 8) = pf[it];
    }
}

// One 128-k chunk: per-warp m32(x)n16 tile of C += hT * W^T, bf16 m16n8k16.
// wb = per-warp base (wn*4096) plus chunk offset (c*2048).
__device__ __forceinline__ void mma_chunk(const unsigned short* __restrict__ wb,
                                          const unsigned short* __restrict__ hTb,
                                          int wm, int g8, int tig, int lane,
                                          float acc[2][4]) {
    const unsigned short* ap0 = hTb + (wm * 16 + g8) * HROW + tig * 2;
    #pragma unroll
    for (int ks = 0; ks < 8; ++ks) {
        const unsigned short* ap = ap0 + ks * 16;
        uint32_t a0 = *reinterpret_cast<const uint32_t*>(ap);
        uint32_t a1 = *reinterpret_cast<const uint32_t*>(ap + 8 * HROW);
        uint32_t a2 = *reinterpret_cast<const uint32_t*>(ap + 8);
        uint32_t a3 = *reinterpret_cast<const uint32_t*>(ap + 8 * HROW + 8);
        #pragma unroll
        for (int j = 0; j < 2; ++j) {
            uint2 bv = *reinterpret_cast<const uint2*>(wb + j * 1024 + ks * 128 + lane * 4);
            asm volatile(
                "mma.sync.aligned.m16n8k16.row.col.f32.bf16.bf16.f32 "
                "{%0,%1,%2,%3}, {%4,%5,%6,%7}, {%8,%9}, {%0,%1,%2,%3};"
                : "+f"(acc[j][0]), "+f"(acc[j][1]), "+f"(acc[j][2]), "+f"(acc[j][3])
                : "r"(a0), "r"(a1), "r"(a2), "r"(a3), "r"(bv.x), "r"(bv.y));
        }
    }
}

__global__ void init_kernel(const float* __restrict__ z) {
    int t = blockIdx.x * blockDim.x + threadIdx.x;
    if (t < BSZ * HID) {
        unsigned short b = __bfloat16_as_ushort(__float2bfloat16(z[t]));
        g_h0[t] = b;
        g_h1[t] = b;
    }
    if (t < BSZ * GSLICES) g_pp[t] = 0.0f;
    if (t < GBGROUPS) { g_bar[t] = 0; g_losspart[t] = 0.0f; }
}

__global__ __launch_bounds__(NTHREADS, 1)
void lstm_kernel(const float* __restrict__ seq,  const float* __restrict__ z,
                 const float* __restrict__ Wih0, const float* __restrict__ Whh0,
                 const float* __restrict__ bih0, const float* __restrict__ bhh0,
                 const float* __restrict__ Wih1, const float* __restrict__ Whh1,
                 const float* __restrict__ bih1, const float* __restrict__ bhh1,
                 const float* __restrict__ Wout, const float* __restrict__ boutp) {
    extern __shared__ __align__(16) char smraw[];
    SmemLayout& S = *reinterpret_cast<SmemLayout*>(smraw);

    const int tid   = threadIdx.x;
    const int g     = blockIdx.x / GSLICES;
    const int s     = blockIdx.x % GSLICES;
    const int bbase = g * BC;
    const int ubase = s * NU;

    // ---- one-time weight load: bf16, packed in B-fragment order ----
    for (int idx = tid; idx < NG * HID; idx += NTHREADS) {
        int nl = idx >> 8, k = idx & 255;
        int grow = ((nl >> 4) << 8) + ubase + (nl & 15);
        int wnq = nl >> 4, j = (nl >> 3) & 1, g8d = nl & 7;
        int c = k >> 7, ks = (k >> 4) & 7, kk = k & 15;
        int r = kk >> 3, tg = (kk & 7) >> 1, b = kk & 1;
        int off = ((((wnq * 2 + c) * 2 + j) * 8 + ks) * 32 + (g8d * 4 + tg)) * 4 + r * 2 + b;
        S.w0 [off] = __bfloat16_as_ushort(__float2bfloat16(Whh0[grow * HID + k]));
        S.w1h[off] = __bfloat16_as_ushort(__float2bfloat16(Whh1[grow * HID + k]));
        S.w1i[off] = __bfloat16_as_ushort(__float2bfloat16(Wih1[grow * HID + k]));
    }
    for (int nl = tid; nl < NG; nl += NTHREADS) {
        int grow = ((nl >> 4) << 8) + ubase + (nl & 15);
        S.wih0 [nl] = Wih0[grow];
        S.bias0[nl] = bih0[grow] + bhh0[grow];
        S.bias1[nl] = bih1[grow] + bhh1[grow];
    }
    if (tid < NU)  S.woutS[tid] = Wout[ubase + tid];
    if (tid == 0)  S.boutv = boutp[0];
    for (int idx = tid; idx < BC * NU; idx += NTHREADS) {
        int m = idx >> 4, u2 = idx & 15;
        float v = z[(bbase + m) * HID + ubase + u2];
        S.c0s[idx] = v;
        S.c1s[idx] = v;
    }
    __syncthreads();

    const int warp = tid >> 5, lane = tid & 31;
    const int wm = warp >> 2, wn = warp & 3;
    const int g8 = lane >> 2, tig = lane & 3;
    const int u = tid & 15, mq = tid >> 4;           // mq 0..15, 2 rows each
    const unsigned short* w0b  = &S.w0 [wn * 4096];
    const unsigned short* w1hb = &S.w1h[wn * 4096];
    const unsigned short* w1ib = &S.w1i[wn * 4096];
    float lossreg = 0.0f;

    uint4 pf[2], pfN[2];
    ldg_h(&g_h0[0], bbase, warp, lane, pfN);

    for (int t = 0; t < TSTEPS; ++t) {
        const int cur = t & 1, nxt = cur ^ 1;
        const unsigned short* h0cur = &g_h0[cur * BSZ * HID];
        const unsigned short* h1cur = &g_h1[cur * BSZ * HID];
        float acc[2][4];

        // ===== layer-0 GEMM over h0_cur (pipelined) =====
        sts_h(S.hT[0], warp, lane, pfN);
        __syncthreads();
        ldg_h(h0cur + 128, bbase, warp, lane, pf);
        #pragma unroll
        for (int j = 0; j < 2; ++j) {
            int col = wn * 16 + j * 8 + 2 * tig;
            acc[j][0] = S.bias0[col];
            acc[j][1] = S.bias0[col + 1];
            acc[j][2] = acc[j][0];
            acc[j][3] = acc[j][1];
        }
        mma_chunk(w0b, S.hT[0], wm, g8, tig, lane, acc);
        sts_h(S.hT[1], warp, lane, pf);
        __syncthreads();
        mma_chunk(w0b + 2048, S.hT[1], wm, g8, tig, lane, acc);

        // ===== barrier B(t-1): pred partials + h1_cur published =====
        bar_wait(g, t * 32);

        // write L0 gates (no pred term yet) -- overlaps pred L2 reads below
        #pragma unroll
        for (int j = 0; j < 2; ++j) {
            int col = wn * 16 + j * 8 + 2 * tig;
            int row = wm * 16 + g8;
            *reinterpret_cast<float2*>(&S.gbuf[row * NG + col]) =
                make_float2(acc[j][0], acc[j][1]);
            *reinterpret_cast<float2*>(&S.gbuf[(row + 8) * NG + col]) =
                make_float2(acc[j][2], acc[j][3]);
        }
        if (tid < BC) {
            float pv;
            if (t == 0) {
                pv = 0.0f;
            } else {
                pv = S.boutv;
                const float* pp = &g_pp[(bbase + tid) * GSLICES];
                #pragma unroll
                for (int q = 0; q < GSLICES; ++q) pv += __ldcg(pp + q);
            }
            S.predvS[tid] = pv;
            if (s == 0 && t > 0) {
                float d = __ldg(&seq[(bbase + tid) * TSTEPS + (t - 1)]) - pv;
                lossreg += d * d;
            }
        }
        __syncthreads();

        ldg_h(h1cur, bbase, warp, lane, pf);   // safe after barrier B(t-1)

        // layer-0 activations (pred term applied inline) -> h0_nxt
        {
            unsigned short* h0n = &g_h0[nxt * BSZ * HID];
            float w_i = S.wih0[u],      w_f = S.wih0[16 + u];
            float w_g = S.wih0[32 + u], w_o = S.wih0[48 + u];
            #pragma unroll
            for (int r = 0; r < 2; ++r) {
                int m = mq * 2 + r;
                float pv = S.predvS[m];
                float gi = S.gbuf[m * NG + u]      + pv * w_i;
                float gf = S.gbuf[m * NG + 16 + u] + pv * w_f;
                float gg = S.gbuf[m * NG + 32 + u] + pv * w_g;
                float go = S.gbuf[m * NG + 48 + u] + pv * w_o;
                float cv = S.c0s[m * NU + u];
                float cn = sigf(gf) * cv + sigf(gi) * tanha(gg);
                float hn = sigf(go) * tanha(cn);
                S.c0s[m * NU + u] = cn;
                h0n[(bbase + m) * HID + ubase + u] = __bfloat16_as_ushort(__float2bfloat16(hn));
            }
        }
        bar_arrive(g);   // barrier A(t): h0_nxt published

        // ===== layer-1 GEMM: h1_cur half (pipelined) =====
        sts_h(S.hT[0], warp, lane, pf);
        __syncthreads();
        ldg_h(h1cur + 128, bbase, warp, lane, pf);
        #pragma unroll
        for (int j = 0; j < 2; ++j) {
            int col = wn * 16 + j * 8 + 2 * tig;
            acc[j][0] = S.bias1[col];
            acc[j][1] = S.bias1[col + 1];
            acc[j][2] = acc[j][0];
            acc[j][3] = acc[j][1];
        }
        mma_chunk(w1hb, S.hT[0], wm, g8, tig, lane, acc);
        sts_h(S.hT[1], warp, lane, pf);
        __syncthreads();
        mma_chunk(w1hb + 2048, S.hT[1], wm, g8, tig, lane, acc);

        // ===== barrier A(t), then h0_nxt half =====
        bar_wait(g, t * 32 + 16);
        const unsigned short* h0nv = &g_h0[nxt * BSZ * HID];
        ldg_h(h0nv, bbase, warp, lane, pf);
        sts_h(S.hT[0], warp, lane, pf);
        __syncthreads();
        ldg_h(h0nv + 128, bbase, warp, lane, pf);
        mma_chunk(w1ib, S.hT[0], wm, g8, tig, lane, acc);
        sts_h(S.hT[1], warp, lane, pf);
        __syncthreads();
        ldg_h(h0nv, bbase, warp, lane, pfN);   // prefetch next step's L0 chunk0
        mma_chunk(w1ib + 2048, S.hT[1], wm, g8, tig, lane, acc);

        // write layer-1 gates
        #pragma unroll
        for (int j = 0; j < 2; ++j) {
            int col = wn * 16 + j * 8 + 2 * tig;
            int row = wm * 16 + g8;
            *reinterpret_cast<float2*>(&S.gbuf[row * NG + col]) =
                make_float2(acc[j][0], acc[j][1]);
            *reinterpret_cast<float2*>(&S.gbuf[(row + 8) * NG + col]) =
                make_float2(acc[j][2], acc[j][3]);
        }
        __syncthreads();

        // layer-1 activations -> h1_nxt + fused pred partials
        {
            unsigned short* h1n = &g_h1[nxt * BSZ * HID];
            float wo = S.woutS[u];
            #pragma unroll
            for (int r = 0; r < 2; ++r) {
                int m = mq * 2 + r;
                float gi = S.gbuf[m * NG + u];
                float gf = S.gbuf[m * NG + 16 + u];
                float gg = S.gbuf[m * NG + 32 + u];
                float go = S.gbuf[m * NG + 48 + u];
                float cv = S.c1s[m * NU + u];
                float cn = sigf(gf) * cv + sigf(gi) * tanha(gg);
                float hn = sigf(go) * tanha(cn);
                S.c1s[m * NU + u] = cn;
                h1n[(bbase + m) * HID + ubase + u] = __bfloat16_as_ushort(__float2bfloat16(hn));
                float v = hn * wo;
                v += __shfl_down_sync(0xffffffffu, v, 8, 16);
                v += __shfl_down_sync(0xffffffffu, v, 4, 16);
                v += __shfl_down_sync(0xffffffffu, v, 2, 16);
                v += __shfl_down_sync(0xffffffffu, v, 1, 16);
                if (u == 0) g_pp[(bbase + m) * GSLICES + s] = v;
            }
        }
        bar_arrive(g);   // barrier B(t)
    }

    // ===== epilogue: final pred + loss =====
    bar_wait(g, TSTEPS * 32);
    if (tid < BC && s == 0) {
        float pv = S.boutv;
        const float* pp = &g_pp[(bbase + tid) * GSLICES];
        #pragma unroll
        for (int q = 0; q < GSLICES; ++q) pv += __ldcg(pp + q);
        float d = __ldg(&seq[(bbase + tid) * TSTEPS + (TSTEPS - 1)]) - pv;
        lossreg += d * d;
    }
    if (s == 0) {
        if (tid < BC) S.lossS[tid] = lossreg;
        __syncthreads();
        if (tid == 0) {
            float sum = 0.0f;
            for (int i = 0; i < BC; ++i) sum += S.lossS[i];
            g_losspart[g] = sum;
        }
    }
}

__global__ void finish_kernel(float* __restrict__ out) {
    float sum = 0.0f;
    for (int i = 0; i < GBGROUPS; ++i) sum += g_losspart[i];
    out[0] = sum / (float)(BSZ * TSTEPS);
}

extern "C" void kernel_launch(void* const* d_in, const int* in_sizes, int n_in,
                              void* d_out, int out_size) {
    const float* seq  = (const float*)d_in[0];
    const float* z    = (const float*)d_in[1];
    const float* Wih0 = (const float*)d_in[3];
    const float* Whh0 = (const float*)d_in[4];
    const float* bih0 = (const float*)d_in[5];
    const float* bhh0 = (const float*)d_in[6];
    const float* Wih1 = (const float*)d_in[7];
    const float* Whh1 = (const float*)d_in[8];
    const float* bih1 = (const float*)d_in[9];
    const float* bhh1 = (const float*)d_in[10];
    const float* Wout = (const float*)d_in[11];
    const float* bout = (const float*)d_in[12];

    cudaFuncSetAttribute(lstm_kernel, cudaFuncAttributeMaxDynamicSharedMemorySize,
                         (int)sizeof(SmemLayout));

    init_kernel<<<(BSZ * HID + 255) / 256, 256>>>(z);
    lstm_kernel<<<NCTA, NTHREADS, sizeof(SmemLayout)>>>(
        seq, z, Wih0, Whh0, bih0, bhh0, Wih1, Whh1, bih1, bhh1, Wout, bout);
    finish_kernel<<<1, 1>>>((float*)d_out);
}

// round 15
// speedup vs baseline: 1.5637x; 1.5637x over previous
#include <cuda_runtime.h>
#include <cuda_bf16.h>
#include <cstdint>

// Problem constants
#define BSZ      256
#define TSTEPS   512
#define HID      256
#define GBGROUPS 8
#define GSLICES  16
#define NCTA     128
#define BC       32
#define NU       16
#define NG       64
#define NTHREADS 128
#define HROW     136    // hT row stride in bf16 elems (128 + 8 pad)

// Persistent scratch ---------------------------------------------------------
__device__ unsigned short g_h0[2 * BSZ * HID];   // bf16 bits
__device__ unsigned short g_h1[2 * BSZ * HID];   // bf16 bits
__device__ float g_pp[BSZ * GSLICES];
__device__ float g_losspart[GBGROUPS];
__device__ int   g_bar[GBGROUPS];

// Shared memory --------------------------------------------------------------
// Weights pre-packed in m16n8k16 B-fragment order:
//   [wn:2][c:2][j:4][ks:8][lane:32][r:2][b:2]  (bf16), 16384 elems / matrix
struct SmemLayout {
    unsigned short w0 [16384];   // Whh_l0   32KB
    unsigned short w1h[16384];   // Whh_l1   32KB
    unsigned short w1i[16384];   // Wih_l1   32KB
    unsigned short hT [2][32 * HROW];  // double-buffered staged h  17KB
    float gbuf[BC * NG];
    float c0s [BC * NU];
    float c1s [BC * NU];
    float predvS[BC];
    float wih0 [NG];
    float bias0[NG];
    float bias1[NG];
    float woutS[NU];
    float lossS[BC];
    float boutv;
};

__device__ __forceinline__ float tanha(float x) {
    float r;
    asm("tanh.approx.f32 %0, %1;" : "=f"(r) : "f"(x));
    return r;
}
__device__ __forceinline__ float sigf(float x) {
    return 0.5f * tanha(0.5f * x) + 0.5f;
}

__device__ __forceinline__ void bar_arrive(int g) {
    __threadfence();
    __syncthreads();
    if (threadIdx.x == 0) atomicAdd(&g_bar[g], 1);
}
__device__ __forceinline__ void bar_wait(int g, int target) {
    if (threadIdx.x == 0) {
        while (((volatile int*)g_bar)[g] < target) { __nanosleep(32); }
    }
    __syncthreads();
}

// LDG 32x128 bf16 chunk into registers (4 warps, 8 rows/warp, 2 rows/iter)
__device__ __forceinline__ void ldg_h(const unsigned short* __restrict__ src,
                                      int bbase, int w, int lane, uint4 pf[4]) {
    int half = lane >> 4, kq = lane & 15;
    #pragma unroll
    for (int it = 0; it < 4; ++it) {
        int m = w * 8 + it * 2 + half;
        pf[it] = __ldcg(reinterpret_cast<const uint4*>(src + (bbase + m) * HID) + kq);
    }
}
__device__ __forceinline__ void sts_h(unsigned short* __restrict__ buf,
                                      int w, int lane, const uint4 pf[4]) {
    int half = lane >> 4, kq = lane & 15;
    #pragma unroll
    for (int it = 0; it < 4; ++it) {
        int m = w * 8 + it * 2 + half;
        *reinterpret_cast<uint4*>(buf + m * HROW + kq * 8) = pf[it];
    }
}

// One 128-k chunk: acc[32x64 tile] += hT * W^T via bf16 mma.m16n8k16
__device__ __forceinline__ void mma_chunk(const unsigned short* __restrict__ wb,
                                          const unsigned short* __restrict__ hTb,
                                          int wm, int g8, int tig, int lane,
                                          float acc[4][4]) {
    const unsigned short* ap0 = hTb + (wm * 16 + g8) * HROW + tig * 2;
    #pragma unroll
    for (int ks = 0; ks < 8; ++ks) {
        const unsigned short* ap = ap0 + ks * 16;
        uint32_t a0 = *reinterpret_cast<const uint32_t*>(ap);
        uint32_t a1 = *reinterpret_cast<const uint32_t*>(ap + 8 * HROW);
        uint32_t a2 = *reinterpret_cast<const uint32_t*>(ap + 8);
        uint32_t a3 = *reinterpret_cast<const uint32_t*>(ap + 8 * HROW + 8);
        #pragma unroll
        for (int j = 0; j < 4; ++j) {
            uint2 bv = *reinterpret_cast<const uint2*>(wb + ((j * 8 + ks) * 32 + lane) * 4);
            asm volatile(
                "mma.sync.aligned.m16n8k16.row.col.f32.bf16.bf16.f32 "
                "{%0,%1,%2,%3}, {%4,%5,%6,%7}, {%8,%9}, {%0,%1,%2,%3};"
                : "+f"(acc[j][0]), "+f"(acc[j][1]), "+f"(acc[j][2]), "+f"(acc[j][3])
                : "r"(a0), "r"(a1), "r"(a2), "r"(a3), "r"(bv.x), "r"(bv.y));
        }
    }
}

__global__ void init_kernel(const float* __restrict__ z) {
    int t = blockIdx.x * blockDim.x + threadIdx.x;
    if (t < BSZ * HID) {
        unsigned short b = __bfloat16_as_ushort(__float2bfloat16(z[t]));
        g_h0[t] = b;
        g_h1[t] = b;
    }
    if (t < BSZ * GSLICES) g_pp[t] = 0.0f;
    if (t < GBGROUPS) { g_bar[t] = 0; g_losspart[t] = 0.0f; }
}

__global__ __launch_bounds__(NTHREADS, 1)
void lstm_kernel(const float* __restrict__ seq,  const float* __restrict__ z,
                 const float* __restrict__ Wih0, const float* __restrict__ Whh0,
                 const float* __restrict__ bih0, const float* __restrict__ bhh0,
                 const float* __restrict__ Wih1, const float* __restrict__ Whh1,
                 const float* __restrict__ bih1, const float* __restrict__ bhh1,
                 const float* __restrict__ Wout, const float* __restrict__ boutp) {
    extern __shared__ __align__(16) char smraw[];
    SmemLayout& S = *reinterpret_cast<SmemLayout*>(smraw);

    const int tid   = threadIdx.x;
    const int g     = blockIdx.x / GSLICES;
    const int s     = blockIdx.x % GSLICES;
    const int bbase = g * BC;
    const int ubase = s * NU;

    // ---- one-time weight load: bf16, packed in B-fragment order ----
    for (int idx = tid; idx < NG * HID; idx += NTHREADS) {
        int nl = idx >> 8, k = idx & 255;
        int grow = ((nl >> 4) << 8) + ubase + (nl & 15);
        int wn = nl >> 5, g8d = nl & 7, j = (nl >> 3) & 3;
        int c = k >> 7, ks = (k >> 4) & 7, kk = k & 15;
        int r = kk >> 3, tg = (kk & 7) >> 1, b = kk & 1;
        int off = ((((wn * 2 + c) * 4 + j) * 8 + ks) * 32 + (g8d * 4 + tg)) * 4 + r * 2 + b;
        S.w0 [off] = __bfloat16_as_ushort(__float2bfloat16(Whh0[grow * HID + k]));
        S.w1h[off] = __bfloat16_as_ushort(__float2bfloat16(Whh1[grow * HID + k]));
        S.w1i[off] = __bfloat16_as_ushort(__float2bfloat16(Wih1[grow * HID + k]));
    }
    for (int nl = tid; nl < NG; nl += NTHREADS) {
        int grow = ((nl >> 4) << 8) + ubase + (nl & 15);
        S.wih0 [nl] = Wih0[grow];
        S.bias0[nl] = bih0[grow] + bhh0[grow];
        S.bias1[nl] = bih1[grow] + bhh1[grow];
    }
    if (tid < NU)  S.woutS[tid] = Wout[ubase + tid];
    if (tid == 0)  S.boutv = boutp[0];
    for (int idx = tid; idx < BC * NU; idx += NTHREADS) {
        int m = idx >> 4, u2 = idx & 15;
        float v = z[(bbase + m) * HID + ubase + u2];
        S.c0s[idx] = v;
        S.c1s[idx] = v;
    }
    __syncthreads();

    const int warp = tid >> 5, lane = tid & 31;
    const int wm = warp >> 1, wn = warp & 1;
    const int g8 = lane >> 2, tig = lane & 3;
    const int u = tid & 15, mq = tid >> 4;    // mq 0..7, 4 rows each
    const unsigned short* w0b  = &S.w0 [wn * 2 * 4096];
    const unsigned short* w1hb = &S.w1h[wn * 2 * 4096];
    const unsigned short* w1ib = &S.w1i[wn * 2 * 4096];
    float lossreg = 0.0f;

    uint4 pf[4], pfN[4];
    ldg_h(&g_h0[0], bbase, warp, lane, pfN);   // prefetch L0 chunk0 for t=0

    for (int t = 0; t < TSTEPS; ++t) {
        const int cur = t & 1, nxt = cur ^ 1;
        const unsigned short* h0cur = &g_h0[cur * BSZ * HID];
        const unsigned short* h1cur = &g_h1[cur * BSZ * HID];
        float acc[4][4];

        // ===== layer-0 GEMM over h0_cur (pipelined) =====
        sts_h(S.hT[0], warp, lane, pfN);
        __syncthreads();
        ldg_h(h0cur + 128, bbase, warp, lane, pf);
        #pragma unroll
        for (int j = 0; j < 4; ++j) {
            int col = wn * 32 + j * 8 + 2 * tig;
            acc[j][0] = S.bias0[col];
            acc[j][1] = S.bias0[col + 1];
            acc[j][2] = acc[j][0];
            acc[j][3] = acc[j][1];
        }
        mma_chunk(w0b, S.hT[0], wm, g8, tig, lane, acc);
        sts_h(S.hT[1], warp, lane, pf);
        __syncthreads();
        mma_chunk(w0b + 4096, S.hT[1], wm, g8, tig, lane, acc);

        // ===== barrier B(t-1): pred partials + h1_cur published =====
        bar_wait(g, t * 32);

        // write raw L0 gates (overlaps pred partial L2 reads below)
        #pragma unroll
        for (int j = 0; j < 4; ++j) {
            int col = wn * 32 + j * 8 + 2 * tig;
            int row = wm * 16 + g8;
            *reinterpret_cast<float2*>(&S.gbuf[row * NG + col]) =
                make_float2(acc[j][0], acc[j][1]);
            *reinterpret_cast<float2*>(&S.gbuf[(row + 8) * NG + col]) =
                make_float2(acc[j][2], acc[j][3]);
        }
        if (tid < BC) {
            float pv;
            if (t == 0) {
                pv = 0.0f;
            } else {
                pv = S.boutv;
                const float* pp = &g_pp[(bbase + tid) * GSLICES];
                #pragma unroll
                for (int q = 0; q < GSLICES; ++q) pv += __ldcg(pp + q);
            }
            S.predvS[tid] = pv;
            if (s == 0 && t > 0) {
                float d = __ldg(&seq[(bbase + tid) * TSTEPS + (t - 1)]) - pv;
                lossreg += d * d;
            }
        }
        __syncthreads();

        ldg_h(h1cur, bbase, warp, lane, pf);   // safe after barrier B(t-1)

        // layer-0 activations (pred term applied inline) -> h0_nxt
        {
            unsigned short* h0n = &g_h0[nxt * BSZ * HID];
            float w_i = S.wih0[u],      w_f = S.wih0[16 + u];
            float w_g = S.wih0[32 + u], w_o = S.wih0[48 + u];
            #pragma unroll
            for (int r = 0; r < 4; ++r) {
                int m = mq * 4 + r;
                float pv = S.predvS[m];
                float gi = S.gbuf[m * NG + u]      + pv * w_i;
                float gf = S.gbuf[m * NG + 16 + u] + pv * w_f;
                float gg = S.gbuf[m * NG + 32 + u] + pv * w_g;
                float go = S.gbuf[m * NG + 48 + u] + pv * w_o;
                float cv = S.c0s[m * NU + u];
                float cn = sigf(gf) * cv + sigf(gi) * tanha(gg);
                float hn = sigf(go) * tanha(cn);
                S.c0s[m * NU + u] = cn;
                h0n[(bbase + m) * HID + ubase + u] = __bfloat16_as_ushort(__float2bfloat16(hn));
            }
        }
        bar_arrive(g);   // barrier A(t): h0_nxt published

        // ===== layer-1 GEMM: h1_cur half (pipelined) =====
        sts_h(S.hT[0], warp, lane, pf);
        __syncthreads();
        ldg_h(h1cur + 128, bbase, warp, lane, pf);
        #pragma unroll
        for (int j = 0; j < 4; ++j) {
            int col = wn * 32 + j * 8 + 2 * tig;
            acc[j][0] = S.bias1[col];
            acc[j][1] = S.bias1[col + 1];
            acc[j][2] = acc[j][0];
            acc[j][3] = acc[j][1];
        }
        mma_chunk(w1hb, S.hT[0], wm, g8, tig, lane, acc);
        sts_h(S.hT[1], warp, lane, pf);
        __syncthreads();
        mma_chunk(w1hb + 4096, S.hT[1], wm, g8, tig, lane, acc);

        // ===== barrier A(t), then h0_nxt half =====
        bar_wait(g, t * 32 + 16);
        const unsigned short* h0nv = &g_h0[nxt * BSZ * HID];
        ldg_h(h0nv, bbase, warp, lane, pf);
        sts_h(S.hT[0], warp, lane, pf);
        __syncthreads();
        ldg_h(h0nv + 128, bbase, warp, lane, pf);
        mma_chunk(w1ib, S.hT[0], wm, g8, tig, lane, acc);
        sts_h(S.hT[1], warp, lane, pf);
        __syncthreads();
        ldg_h(h0nv, bbase, warp, lane, pfN);   // prefetch next step's L0 chunk0
        mma_chunk(w1ib + 4096, S.hT[1], wm, g8, tig, lane, acc);

        // write layer-1 gates
        #pragma unroll
        for (int j = 0; j < 4; ++j) {
            int col = wn * 32 + j * 8 + 2 * tig;
            int row = wm * 16 + g8;
            *reinterpret_cast<float2*>(&S.gbuf[row * NG + col]) =
                make_float2(acc[j][0], acc[j][1]);
            *reinterpret_cast<float2*>(&S.gbuf[(row + 8) * NG + col]) =
                make_float2(acc[j][2], acc[j][3]);
        }
        __syncthreads();

        // layer-1 activations -> h1_nxt + fused pred partials
        {
            unsigned short* h1n = &g_h1[nxt * BSZ * HID];
            float wo = S.woutS[u];
            #pragma unroll
            for (int r = 0; r < 4; ++r) {
                int m = mq * 4 + r;
                float gi = S.gbuf[m * NG + u];
                float gf = S.gbuf[m * NG + 16 + u];
                float gg = S.gbuf[m * NG + 32 + u];
                float go = S.gbuf[m * NG + 48 + u];
                float cv = S.c1s[m * NU + u];
                float cn = sigf(gf) * cv + sigf(gi) * tanha(gg);
                float hn = sigf(go) * tanha(cn);
                S.c1s[m * NU + u] = cn;
                h1n[(bbase + m) * HID + ubase + u] = __bfloat16_as_ushort(__float2bfloat16(hn));
                float v = hn * wo;
                v += __shfl_down_sync(0xffffffffu, v, 8, 16);
                v += __shfl_down_sync(0xffffffffu, v, 4, 16);
                v += __shfl_down_sync(0xffffffffu, v, 2, 16);
                v += __shfl_down_sync(0xffffffffu, v, 1, 16);
                if (u == 0) g_pp[(bbase + m) * GSLICES + s] = v;
            }
        }
        bar_arrive(g);   // barrier B(t)
    }

    // ===== epilogue: final pred + loss =====
    bar_wait(g, TSTEPS * 32);
    if (tid < BC && s == 0) {
        float pv = S.boutv;
        const float* pp = &g_pp[(bbase + tid) * GSLICES];
        #pragma unroll
        for (int q = 0; q < GSLICES; ++q) pv += __ldcg(pp + q);
        float d = __ldg(&seq[(bbase + tid) * TSTEPS + (TSTEPS - 1)]) - pv;
        lossreg += d * d;
    }
    if (s == 0) {
        if (tid < BC) S.lossS[tid] = lossreg;
        __syncthreads();
        if (tid == 0) {
            float sum = 0.0f;
            for (int i = 0; i < BC; ++i) sum += S.lossS[i];
            g_losspart[g] = sum;
        }
    }
}

__global__ void finish_kernel(float* __restrict__ out) {
    float sum = 0.0f;
    for (int i = 0; i < GBGROUPS; ++i) sum += g_losspart[i];
    out[0] = sum / (float)(BSZ * TSTEPS);
}

extern "C" void kernel_launch(void* const* d_in, const int* in_sizes, int n_in,
                              void* d_out, int out_size) {
    const float* seq  = (const float*)d_in[0];
    const float* z    = (const float*)d_in[1];
    const float* Wih0 = (const float*)d_in[3];
    const float* Whh0 = (const float*)d_in[4];
    const float* bih0 = (const float*)d_in[5];
    const float* bhh0 = (const float*)d_in[6];
    const float* Wih1 = (const float*)d_in[7];
    const float* Whh1 = (const float*)d_in[8];
    const float* bih1 = (const float*)d_in[9];
    const float* bhh1 = (const float*)d_in[10];
    const float* Wout = (const float*)d_in[11];
    const float* bout = (const float*)d_in[12];

    cudaFuncSetAttribute(lstm_kernel, cudaFuncAttributeMaxDynamicSharedMemorySize,
                         (int)sizeof(SmemLayout));

    init_kernel<<<(BSZ * HID + 255) / 256, 256>>>(z);
    lstm_kernel<<<NCTA, NTHREADS, sizeof(SmemLayout)>>>(
        seq, z, Wih0, Whh0, bih0, bhh0, Wih1, Whh1, bih1, bhh1, Wout, bout);
    finish_kernel<<<1, 1>>>((float*)d_out);
}

// round 16
// speedup vs baseline: 1.7762x; 1.1359x over previous
#include <cuda_runtime.h>
#include <cuda_bf16.h>
#include <cstdint>

// Problem constants
#define BSZ      256
#define TSTEPS   512
#define HID      256
#define GBGROUPS 8
#define GSLICES  16
#define NCTA     128
#define BC       32
#define NU       16
#define NG       64
#define NTHREADS 128
#define HROW     136    // hT row stride in bf16 elems (128 + 8 pad)

// Persistent scratch ---------------------------------------------------------
__device__ unsigned short g_h0[2 * BSZ * HID];   // bf16 bits
__device__ unsigned short g_h1[2 * BSZ * HID];   // bf16 bits
__device__ float g_losspart[GBGROUPS];
__device__ int   g_bar[GBGROUPS];

// Shared memory --------------------------------------------------------------
// Weights pre-packed in m16n8k16 B-fragment order:
//   [wn:2][c:2][j:4][ks:8][lane:32][r:2][b:2]  (bf16), 16384 elems / matrix
struct SmemLayout {
    unsigned short w0 [16384];
    unsigned short w1h[16384];
    unsigned short w1i[16384];
    unsigned short hT [2][32 * HROW];
    float gbuf[BC * NG];
    float c0s [BC * NU];
    float c1s [BC * NU];
    float predvS[BC];
    float wih0 [NG];
    float bias0[NG];
    float bias1[NG];
    float woutF[HID];     // full W_out row (all 256)
    float lossS[BC];
    float boutv;
};

__device__ __forceinline__ float tanha(float x) {
    float r;
    asm("tanh.approx.f32 %0, %1;" : "=f"(r) : "f"(x));
    return r;
}
__device__ __forceinline__ float sigf(float x) {
    return 0.5f * tanha(0.5f * x) + 0.5f;
}

__device__ __forceinline__ void bar_arrive(int g) {
    __threadfence();
    __syncthreads();
    if (threadIdx.x == 0) atomicAdd(&g_bar[g], 1);
}
__device__ __forceinline__ void bar_wait(int g, int target) {
    if (threadIdx.x == 0) {
        while (((volatile int*)g_bar)[g] < target) { __nanosleep(32); }
    }
    __syncthreads();
}

// LDG 32x128 bf16 chunk into registers (4 warps, 8 rows/warp, 2 rows/iter)
__device__ __forceinline__ void ldg_h(const unsigned short* __restrict__ src,
                                      int bbase, int w, int lane, uint4 pf[4]) {
    int half = lane >> 4, kq = lane & 15;
    #pragma unroll
    for (int it = 0; it < 4; ++it) {
        int m = w * 8 + it * 2 + half;
        pf[it] = __ldcg(reinterpret_cast<const uint4*>(src + (bbase + m) * HID) + kq);
    }
}
__device__ __forceinline__ void sts_h(unsigned short* __restrict__ buf,
                                      int w, int lane, const uint4 pf[4]) {
    int half = lane >> 4, kq = lane & 15;
    #pragma unroll
    for (int it = 0; it < 4; ++it) {
        int m = w * 8 + it * 2 + half;
        *reinterpret_cast<uint4*>(buf + m * HROW + kq * 8) = pf[it];
    }
}

// One 128-k chunk: acc[32x64 tile] += hT * W^T via bf16 mma.m16n8k16.
// A-fragments via ldmatrix.x4 (lmaddr = per-lane shared byte address).
__device__ __forceinline__ void mma_chunk(const unsigned short* __restrict__ wb,
                                          uint32_t lmaddr, int lane,
                                          float acc[4][4]) {
    #pragma unroll
    for (int ks = 0; ks < 8; ++ks) {
        uint32_t a0, a1, a2, a3;
        asm volatile(
            "ldmatrix.sync.aligned.m8n8.x4.shared.b16 {%0,%1,%2,%3}, [%4];"
            : "=r"(a0), "=r"(a1), "=r"(a2), "=r"(a3)
            : "r"(lmaddr + ks * 32));
        #pragma unroll
        for (int j = 0; j < 4; ++j) {
            uint2 bv = *reinterpret_cast<const uint2*>(wb + ((j * 8 + ks) * 32 + lane) * 4);
            asm volatile(
                "mma.sync.aligned.m16n8k16.row.col.f32.bf16.bf16.f32 "
                "{%0,%1,%2,%3}, {%4,%5,%6,%7}, {%8,%9}, {%0,%1,%2,%3};"
                : "+f"(acc[j][0]), "+f"(acc[j][1]), "+f"(acc[j][2]), "+f"(acc[j][3])
                : "r"(a0), "r"(a1), "r"(a2), "r"(a3), "r"(bv.x), "r"(bv.y));
        }
    }
}

__global__ void init_kernel(const float* __restrict__ z) {
    int t = blockIdx.x * blockDim.x + threadIdx.x;
    if (t < BSZ * HID) {
        unsigned short b = __bfloat16_as_ushort(__float2bfloat16(z[t]));
        g_h0[t] = b;
        g_h1[t] = b;
    }
    if (t < GBGROUPS) { g_bar[t] = 0; g_losspart[t] = 0.0f; }
}

__global__ __launch_bounds__(NTHREADS, 1)
void lstm_kernel(const float* __restrict__ seq,  const float* __restrict__ z,
                 const float* __restrict__ Wih0, const float* __restrict__ Whh0,
                 const float* __restrict__ bih0, const float* __restrict__ bhh0,
                 const float* __restrict__ Wih1, const float* __restrict__ Whh1,
                 const float* __restrict__ bih1, const float* __restrict__ bhh1,
                 const float* __restrict__ Wout, const float* __restrict__ boutp) {
    extern __shared__ __align__(16) char smraw[];
    SmemLayout& S = *reinterpret_cast<SmemLayout*>(smraw);

    const int tid   = threadIdx.x;
    const int g     = blockIdx.x / GSLICES;
    const int s     = blockIdx.x % GSLICES;
    const int bbase = g * BC;
    const int ubase = s * NU;

    // ---- one-time weight load: bf16, packed in B-fragment order ----
    for (int idx = tid; idx < NG * HID; idx += NTHREADS) {
        int nl = idx >> 8, k = idx & 255;
        int grow = ((nl >> 4) << 8) + ubase + (nl & 15);
        int wn = nl >> 5, g8d = nl & 7, j = (nl >> 3) & 3;
        int c = k >> 7, ks = (k >> 4) & 7, kk = k & 15;
        int r = kk >> 3, tg = (kk & 7) >> 1, b = kk & 1;
        int off = ((((wn * 2 + c) * 4 + j) * 8 + ks) * 32 + (g8d * 4 + tg)) * 4 + r * 2 + b;
        S.w0 [off] = __bfloat16_as_ushort(__float2bfloat16(Whh0[grow * HID + k]));
        S.w1h[off] = __bfloat16_as_ushort(__float2bfloat16(Whh1[grow * HID + k]));
        S.w1i[off] = __bfloat16_as_ushort(__float2bfloat16(Wih1[grow * HID + k]));
    }
    for (int nl = tid; nl < NG; nl += NTHREADS) {
        int grow = ((nl >> 4) << 8) + ubase + (nl & 15);
        S.wih0 [nl] = Wih0[grow];
        S.bias0[nl] = bih0[grow] + bhh0[grow];
        S.bias1[nl] = bih1[grow] + bhh1[grow];
    }
    for (int k = tid; k < HID; k += NTHREADS) S.woutF[k] = Wout[k];
    if (tid == 0) S.boutv = boutp[0];
    for (int idx = tid; idx < BC * NU; idx += NTHREADS) {
        int m = idx >> 4, u2 = idx & 15;
        float v = z[(bbase + m) * HID + ubase + u2];
        S.c0s[idx] = v;
        S.c1s[idx] = v;
    }
    __syncthreads();

    const int warp = tid >> 5, lane = tid & 31;
    const int wm = warp >> 1, wn = warp & 1;
    const int g8 = lane >> 2, tig = lane & 3;
    const int u = tid & 15, mq = tid >> 4;
    const int kq = lane & 15;
    const unsigned short* w0b  = &S.w0 [wn * 2 * 4096];
    const unsigned short* w1hb = &S.w1h[wn * 2 * 4096];
    const unsigned short* w1ib = &S.w1i[wn * 2 * 4096];

    // ldmatrix per-lane byte offset into an hT buffer
    const uint32_t lmoff = ((uint32_t)((wm * 16 + (lane & 15)) * HROW + (lane >> 4) * 8)) * 2u;
    const uint32_t hT0a = (uint32_t)__cvta_generic_to_shared(S.hT[0]) + lmoff;
    const uint32_t hT1a = (uint32_t)__cvta_generic_to_shared(S.hT[1]) + lmoff;

    // W_out slice for local pred dot (registers, constant across steps)
    float wf0[8], wf1[8];
    #pragma unroll
    for (int q = 0; q < 8; ++q) {
        wf0[q] = S.woutF[kq * 8 + q];
        wf1[q] = S.woutF[128 + kq * 8 + q];
    }
    const float boutv = S.boutv;
    float lossreg = 0.0f;

    uint4 pfN[4], pfA[4], pfB[4];
    ldg_h(&g_h0[0], bbase, warp, lane, pfN);   // prefetch L0 chunk0 for t=0

    for (int t = 0; t < TSTEPS; ++t) {
        const int cur = t & 1, nxt = cur ^ 1;
        const unsigned short* h0cur = &g_h0[cur * BSZ * HID];
        const unsigned short* h1cur = &g_h1[cur * BSZ * HID];
        float acc[4][4];

        // ===== layer-0 GEMM over h0_cur (pipelined) =====
        sts_h(S.hT[0], warp, lane, pfN);
        __syncthreads();
        ldg_h(h0cur + 128, bbase, warp, lane, pfA);
        #pragma unroll
        for (int j = 0; j < 4; ++j) {
            int col = wn * 32 + j * 8 + 2 * tig;
            acc[j][0] = S.bias0[col];
            acc[j][1] = S.bias0[col + 1];
            acc[j][2] = acc[j][0];
            acc[j][3] = acc[j][1];
        }
        mma_chunk(w0b, hT0a, lane, acc);
        sts_h(S.hT[1], warp, lane, pfA);
        __syncthreads();
        mma_chunk(w0b + 4096, hT1a, lane, acc);

        // ===== barrier B(t-1): h1_cur published =====
        bar_wait(g, t * 32);

        // write raw L0 gates
        #pragma unroll
        for (int j = 0; j < 4; ++j) {
            int col = wn * 32 + j * 8 + 2 * tig;
            int row = wm * 16 + g8;
            *reinterpret_cast<float2*>(&S.gbuf[row * NG + col]) =
                make_float2(acc[j][0], acc[j][1]);
            *reinterpret_cast<float2*>(&S.gbuf[(row + 8) * NG + col]) =
                make_float2(acc[j][2], acc[j][3]);
        }

        // load BOTH h1_cur chunks; stage; compute pred locally from registers
        ldg_h(h1cur,       bbase, warp, lane, pfA);
        ldg_h(h1cur + 128, bbase, warp, lane, pfB);
        sts_h(S.hT[0], warp, lane, pfA);
        sts_h(S.hT[1], warp, lane, pfB);
        {
            float pr[4];
            #pragma unroll
            for (int it = 0; it < 4; ++it) {
                float v = 0.0f;
                const uint32_t* qa = reinterpret_cast<const uint32_t*>(&pfA[it]);
                const uint32_t* qb = reinterpret_cast<const uint32_t*>(&pfB[it]);
                #pragma unroll
                for (int q = 0; q < 4; ++q) {
                    float2 fa = __bfloat1622float2(
                        *reinterpret_cast<const __nv_bfloat162*>(&qa[q]));
                    float2 fb = __bfloat1622float2(
                        *reinterpret_cast<const __nv_bfloat162*>(&qb[q]));
                    v += fa.x * wf0[q * 2] + fa.y * wf0[q * 2 + 1];
                    v += fb.x * wf1[q * 2] + fb.y * wf1[q * 2 + 1];
                }
                v += __shfl_down_sync(0xffffffffu, v, 8, 16);
                v += __shfl_down_sync(0xffffffffu, v, 4, 16);
                v += __shfl_down_sync(0xffffffffu, v, 2, 16);
                v += __shfl_down_sync(0xffffffffu, v, 1, 16);
                pr[it] = v;
            }
            if (kq == 0) {
                int half = lane >> 4;
                #pragma unroll
                for (int it = 0; it < 4; ++it) {
                    int m = warp * 8 + it * 2 + half;
                    S.predvS[m] = (t == 0) ? 0.0f : (pr[it] + boutv);
                }
            }
        }
        __syncthreads();   // gbuf + predvS + hT visible

        // loss (slice 0 only)
        if (s == 0 && t > 0 && tid < BC) {
            float d = __ldg(&seq[(bbase + tid) * TSTEPS + (t - 1)]) - S.predvS[tid];
            lossreg += d * d;
        }

        // layer-0 activations (pred term inline) -> h0_nxt
        {
            unsigned short* h0n = &g_h0[nxt * BSZ * HID];
            float w_i = S.wih0[u],      w_f = S.wih0[16 + u];
            float w_g = S.wih0[32 + u], w_o = S.wih0[48 + u];
            #pragma unroll
            for (int r = 0; r < 4; ++r) {
                int m = mq * 4 + r;
                float pv = S.predvS[m];
                float gi = S.gbuf[m * NG + u]      + pv * w_i;
                float gf = S.gbuf[m * NG + 16 + u] + pv * w_f;
                float gg = S.gbuf[m * NG + 32 + u] + pv * w_g;
                float go = S.gbuf[m * NG + 48 + u] + pv * w_o;
                float cv = S.c0s[m * NU + u];
                float cn = sigf(gf) * cv + sigf(gi) * tanha(gg);
                float hn = sigf(go) * tanha(cn);
                S.c0s[m * NU + u] = cn;
                h0n[(bbase + m) * HID + ubase + u] = __bfloat16_as_ushort(__float2bfloat16(hn));
            }
        }
        bar_arrive(g);   // barrier A(t): h0_nxt published

        // ===== layer-1 GEMM: both h1_cur chunks (already staged) =====
        #pragma unroll
        for (int j = 0; j < 4; ++j) {
            int col = wn * 32 + j * 8 + 2 * tig;
            acc[j][0] = S.bias1[col];
            acc[j][1] = S.bias1[col + 1];
            acc[j][2] = acc[j][0];
            acc[j][3] = acc[j][1];
        }
        mma_chunk(w1hb,        hT0a, lane, acc);
        mma_chunk(w1hb + 4096, hT1a, lane, acc);

        // ===== barrier A(t), then h0_nxt half =====
        bar_wait(g, t * 32 + 16);
        const unsigned short* h0nv = &g_h0[nxt * BSZ * HID];
        ldg_h(h0nv, bbase, warp, lane, pfA);
        sts_h(S.hT[0], warp, lane, pfA);
        __syncthreads();
        ldg_h(h0nv + 128, bbase, warp, lane, pfB);
        mma_chunk(w1ib, hT0a, lane, acc);
        sts_h(S.hT[1], warp, lane, pfB);
        __syncthreads();
        ldg_h(h0nv, bbase, warp, lane, pfN);   // prefetch next step's L0 chunk0
        mma_chunk(w1ib + 4096, hT1a, lane, acc);

        // write layer-1 gates
        #pragma unroll
        for (int j = 0; j < 4; ++j) {
            int col = wn * 32 + j * 8 + 2 * tig;
            int row = wm * 16 + g8;
            *reinterpret_cast<float2*>(&S.gbuf[row * NG + col]) =
                make_float2(acc[j][0], acc[j][1]);
            *reinterpret_cast<float2*>(&S.gbuf[(row + 8) * NG + col]) =
                make_float2(acc[j][2], acc[j][3]);
        }
        __syncthreads();

        // layer-1 activations -> h1_nxt
        {
            unsigned short* h1n = &g_h1[nxt * BSZ * HID];
            #pragma unroll
            for (int r = 0; r < 4; ++r) {
                int m = mq * 4 + r;
                float gi = S.gbuf[m * NG + u];
                float gf = S.gbuf[m * NG + 16 + u];
                float gg = S.gbuf[m * NG + 32 + u];
                float go = S.gbuf[m * NG + 48 + u];
                float cv = S.c1s[m * NU + u];
                float cn = sigf(gf) * cv + sigf(gi) * tanha(gg);
                float hn = sigf(go) * tanha(cn);
                S.c1s[m * NU + u] = cn;
                h1n[(bbase + m) * HID + ubase + u] = __bfloat16_as_ushort(__float2bfloat16(hn));
            }
        }
        bar_arrive(g);   // barrier B(t)
    }

    // ===== epilogue: final pred (from final h1, buffer 0) + loss =====
    bar_wait(g, TSTEPS * 32);
    if (s == 0) {
        ldg_h(&g_h1[0],       bbase, warp, lane, pfA);
        ldg_h(&g_h1[0] + 128, bbase, warp, lane, pfB);
        float pr[4];
        #pragma unroll
        for (int it = 0; it < 4; ++it) {
            float v = 0.0f;
            const uint32_t* qa = reinterpret_cast<const uint32_t*>(&pfA[it]);
            const uint32_t* qb = reinterpret_cast<const uint32_t*>(&pfB[it]);
            #pragma unroll
            for (int q = 0; q < 4; ++q) {
                float2 fa = __bfloat1622float2(
                    *reinterpret_cast<const __nv_bfloat162*>(&qa[q]));
                float2 fb = __bfloat1622float2(
                    *reinterpret_cast<const __nv_bfloat162*>(&qb[q]));
                v += fa.x * wf0[q * 2] + fa.y * wf0[q * 2 + 1];
                v += fb.x * wf1[q * 2] + fb.y * wf1[q * 2 + 1];
            }
            v += __shfl_down_sync(0xffffffffu, v, 8, 16);
            v += __shfl_down_sync(0xffffffffu, v, 4, 16);
            v += __shfl_down_sync(0xffffffffu, v, 2, 16);
            v += __shfl_down_sync(0xffffffffu, v, 1, 16);
            pr[it] = v;
        }
        if (kq == 0) {
            int half = lane >> 4;
            #pragma unroll
            for (int it = 0; it < 4; ++it) {
                int m = warp * 8 + it * 2 + half;
                S.predvS[m] = pr[it] + boutv;
            }
        }
        __syncthreads();
        if (tid < BC) {
            float d = __ldg(&seq[(bbase + tid) * TSTEPS + (TSTEPS - 1)]) - S.predvS[tid];
            lossreg += d * d;
            S.lossS[tid] = lossreg;
        }
        __syncthreads();
        if (tid == 0) {
            float sum = 0.0f;
            for (int i = 0; i < BC; ++i) sum += S.lossS[i];
            g_losspart[g] = sum;
        }
    }
}

__global__ void finish_kernel(float* __restrict__ out) {
    float sum = 0.0f;
    for (int i = 0; i < GBGROUPS; ++i) sum += g_losspart[i];
    out[0] = sum / (float)(BSZ * TSTEPS);
}

extern "C" void kernel_launch(void* const* d_in, const int* in_sizes, int n_in,
                              void* d_out, int out_size) {
    const float* seq  = (const float*)d_in[0];
    const float* z    = (const float*)d_in[1];
    const float* Wih0 = (const float*)d_in[3];
    const float* Whh0 = (const float*)d_in[4];
    const float* bih0 = (const float*)d_in[5];
    const float* bhh0 = (const float*)d_in[6];
    const float* Wih1 = (const float*)d_in[7];
    const float* Whh1 = (const float*)d_in[8];
    const float* bih1 = (const float*)d_in[9];
    const float* bhh1 = (const float*)d_in[10];
    const float* Wout = (const float*)d_in[11];
    const float* bout = (const float*)d_in[12];

    cudaFuncSetAttribute(lstm_kernel, cudaFuncAttributeMaxDynamicSharedMemorySize,
                         (int)sizeof(SmemLayout));

    init_kernel<<<(BSZ * HID + 255) / 256, 256>>>(z);
    lstm_kernel<<<NCTA, NTHREADS, sizeof(SmemLayout)>>>(
        seq, z, Wih0, Whh0, bih0, bhh0, Wih1, Whh1, bih1, bhh1, Wout, bout);
    finish_kernel<<<1, 1>>>((float*)d_out);
}

// round 17
// speedup vs baseline: 2.1647x; 1.2187x over previous
#include <cuda_runtime.h>
#include <cuda_bf16.h>
#include <cstdint>

// Problem constants
#define BSZ      256
#define TSTEPS   512
#define HID      256
#define GBGROUPS 8
#define GSLICES  16
#define NCTA     128
#define BC       32
#define NU       16
#define NG       64
#define NTHREADS 128
#define HROW     136    // hT row stride in bf16 elems (128 + 8 pad)
#define GROW     80     // gbuf row stride in floats (64 + 16 pad)

// Persistent scratch ---------------------------------------------------------
__device__ unsigned short g_h0[2 * BSZ * HID];   // bf16 bits
__device__ unsigned short g_h1[2 * BSZ * HID];   // bf16 bits
__device__ float g_losspart[GBGROUPS];
__device__ int   g_bar[GBGROUPS];

// Shared memory --------------------------------------------------------------
// Weights pre-packed in m16n8k16 B-fragment order:
//   [wn:2][c:2][j:4][ks:8][lane:32][r:2][b:2]  (bf16), 16384 elems / matrix
struct SmemLayout {
    unsigned short w0 [16384];
    unsigned short w1h[16384];
    unsigned short w1i[16384];
    unsigned short hT [2][32 * HROW];
    float gbuf[BC * GROW];
    float c0s [BC * NU];
    float c1s [BC * NU];
    float predvS[BC];
    float wih0 [NG];
    float bias0[NG];
    float bias1[NG];
    float woutF[HID];
    float lossS[BC];
    float boutv;
};

__device__ __forceinline__ float tanha(float x) {
    float r;
    asm("tanh.approx.f32 %0, %1;" : "=f"(r) : "f"(x));
    return r;
}
__device__ __forceinline__ float sigf(float x) {
    return 0.5f * tanha(0.5f * x) + 0.5f;
}

__device__ __forceinline__ void bar_arrive(int g) {
    __threadfence();
    __syncthreads();
    if (threadIdx.x == 0) atomicAdd(&g_bar[g], 1);
}
__device__ __forceinline__ void bar_wait(int g, int target) {
    if (threadIdx.x == 0) {
        while (((volatile int*)g_bar)[g] < target) {}
    }
    __syncthreads();
}

// LDG 32x128 bf16 chunk into registers (4 warps, 8 rows/warp, 2 rows/iter)
__device__ __forceinline__ void ldg_h(const unsigned short* __restrict__ src,
                                      int bbase, int w, int lane, uint4 pf[4]) {
    int half = lane >> 4, kq = lane & 15;
    #pragma unroll
    for (int it = 0; it < 4; ++it) {
        int m = w * 8 + it * 2 + half;
        pf[it] = __ldcg(reinterpret_cast<const uint4*>(src + (bbase + m) * HID) + kq);
    }
}
__device__ __forceinline__ void sts_h(unsigned short* __restrict__ buf,
                                      int w, int lane, const uint4 pf[4]) {
    int half = lane >> 4, kq = lane & 15;
    #pragma unroll
    for (int it = 0; it < 4; ++it) {
        int m = w * 8 + it * 2 + half;
        *reinterpret_cast<uint4*>(buf + m * HROW + kq * 8) = pf[it];
    }
}

// One 128-k chunk: acc[32x64 tile] += hT * W^T via bf16 mma.m16n8k16.
__device__ __forceinline__ void mma_chunk(const unsigned short* __restrict__ wb,
                                          uint32_t lmaddr, int lane,
                                          float acc[4][4]) {
    #pragma unroll
    for (int ks = 0; ks < 8; ++ks) {
        uint32_t a0, a1, a2, a3;
        asm volatile(
            "ldmatrix.sync.aligned.m8n8.x4.shared.b16 {%0,%1,%2,%3}, [%4];"
            : "=r"(a0), "=r"(a1), "=r"(a2), "=r"(a3)
            : "r"(lmaddr + ks * 32));
        #pragma unroll
        for (int j = 0; j < 4; ++j) {
            uint2 bv = *reinterpret_cast<const uint2*>(wb + ((j * 8 + ks) * 32 + lane) * 4);
            asm volatile(
                "mma.sync.aligned.m16n8k16.row.col.f32.bf16.bf16.f32 "
                "{%0,%1,%2,%3}, {%4,%5,%6,%7}, {%8,%9}, {%0,%1,%2,%3};"
                : "+f"(acc[j][0]), "+f"(acc[j][1]), "+f"(acc[j][2]), "+f"(acc[j][3])
                : "r"(a0), "r"(a1), "r"(a2), "r"(a3), "r"(bv.x), "r"(bv.y));
        }
    }
}

__global__ void init_kernel(const float* __restrict__ z) {
    int t = blockIdx.x * blockDim.x + threadIdx.x;
    if (t < BSZ * HID) {
        unsigned short b = __bfloat16_as_ushort(__float2bfloat16(z[t]));
        g_h0[t] = b;
        g_h1[t] = b;
    }
    if (t < GBGROUPS) { g_bar[t] = 0; g_losspart[t] = 0.0f; }
}

__global__ __launch_bounds__(NTHREADS, 1)
void lstm_kernel(const float* __restrict__ seq,  const float* __restrict__ z,
                 const float* __restrict__ Wih0, const float* __restrict__ Whh0,
                 const float* __restrict__ bih0, const float* __restrict__ bhh0,
                 const float* __restrict__ Wih1, const float* __restrict__ Whh1,
                 const float* __restrict__ bih1, const float* __restrict__ bhh1,
                 const float* __restrict__ Wout, const float* __restrict__ boutp) {
    extern __shared__ __align__(16) char smraw[];
    SmemLayout& S = *reinterpret_cast<SmemLayout*>(smraw);

    const int tid   = threadIdx.x;
    const int g     = blockIdx.x / GSLICES;
    const int s     = blockIdx.x % GSLICES;
    const int bbase = g * BC;
    const int ubase = s * NU;

    // ---- one-time weight load: bf16, packed in B-fragment order ----
    for (int idx = tid; idx < NG * HID; idx += NTHREADS) {
        int nl = idx >> 8, k = idx & 255;
        int grow = ((nl >> 4) << 8) + ubase + (nl & 15);
        int wn = nl >> 5, g8d = nl & 7, j = (nl >> 3) & 3;
        int c = k >> 7, ks = (k >> 4) & 7, kk = k & 15;
        int r = kk >> 3, tg = (kk & 7) >> 1, b = kk & 1;
        int off = ((((wn * 2 + c) * 4 + j) * 8 + ks) * 32 + (g8d * 4 + tg)) * 4 + r * 2 + b;
        S.w0 [off] = __bfloat16_as_ushort(__float2bfloat16(Whh0[grow * HID + k]));
        S.w1h[off] = __bfloat16_as_ushort(__float2bfloat16(Whh1[grow * HID + k]));
        S.w1i[off] = __bfloat16_as_ushort(__float2bfloat16(Wih1[grow * HID + k]));
    }
    for (int nl = tid; nl < NG; nl += NTHREADS) {
        int grow = ((nl >> 4) << 8) + ubase + (nl & 15);
        S.wih0 [nl] = Wih0[grow];
        S.bias0[nl] = bih0[grow] + bhh0[grow];
        S.bias1[nl] = bih1[grow] + bhh1[grow];
    }
    for (int k = tid; k < HID; k += NTHREADS) S.woutF[k] = Wout[k];
    if (tid == 0) S.boutv = boutp[0];
    for (int idx = tid; idx < BC * NU; idx += NTHREADS) {
        int m = idx >> 4, u2 = idx & 15;
        float v = z[(bbase + m) * HID + ubase + u2];
        S.c0s[idx] = v;
        S.c1s[idx] = v;
    }
    __syncthreads();

    const int warp = tid >> 5, lane = tid & 31;
    const int wm = warp >> 1, wn = warp & 1;
    const int g8 = lane >> 2, tig = lane & 3;
    const int kq = lane & 15;
    const int up = (tid & 7) * 2;     // activation u-pair
    const int mr = tid >> 3;          // activation row base (0..15)
    const unsigned short* w0b  = &S.w0 [wn * 2 * 4096];
    const unsigned short* w1hb = &S.w1h[wn * 2 * 4096];
    const unsigned short* w1ib = &S.w1i[wn * 2 * 4096];

    const uint32_t lmoff = ((uint32_t)((wm * 16 + (lane & 15)) * HROW + (lane >> 4) * 8)) * 2u;
    const uint32_t hT0a = (uint32_t)__cvta_generic_to_shared(S.hT[0]) + lmoff;
    const uint32_t hT1a = (uint32_t)__cvta_generic_to_shared(S.hT[1]) + lmoff;

    // W_out slice for local pred dot
    float wf0[8], wf1[8];
    #pragma unroll
    for (int q = 0; q < 8; ++q) {
        wf0[q] = S.woutF[kq * 8 + q];
        wf1[q] = S.woutF[128 + kq * 8 + q];
    }
    const float boutv = S.boutv;
    float lossreg = 0.0f;

    uint4 pfA[4], pfB[4];
    // prologue: stage h0(0) into hT[0..1]
    ldg_h(&g_h0[0],       bbase, warp, lane, pfA);
    ldg_h(&g_h0[0] + 128, bbase, warp, lane, pfB);
    sts_h(S.hT[0], warp, lane, pfA);
    sts_h(S.hT[1], warp, lane, pfB);
    __syncthreads();

    for (int t = 0; t < TSTEPS; ++t) {
        const int cur = t & 1, nxt = cur ^ 1;
        const unsigned short* h1cur = &g_h1[cur * BSZ * HID];
        float acc[4][4];

        // ===== layer-0 GEMM: hT already holds h0_cur =====
        #pragma unroll
        for (int j = 0; j < 4; ++j) {
            int col = wn * 32 + j * 8 + 2 * tig;
            acc[j][0] = S.bias0[col];
            acc[j][1] = S.bias0[col + 1];
            acc[j][2] = acc[j][0];
            acc[j][3] = acc[j][1];
        }
        mma_chunk(w0b,        hT0a, lane, acc);
        mma_chunk(w0b + 4096, hT1a, lane, acc);

        // ===== barrier B(t-1): h1_cur published =====
        bar_wait(g, t * 32);
        ldg_h(h1cur,       bbase, warp, lane, pfA);
        ldg_h(h1cur + 128, bbase, warp, lane, pfB);

        // write raw L0 gates (under LDG latency)
        #pragma unroll
        for (int j = 0; j < 4; ++j) {
            int col = wn * 32 + j * 8 + 2 * tig;
            int row = wm * 16 + g8;
            *reinterpret_cast<float2*>(&S.gbuf[row * GROW + col]) =
                make_float2(acc[j][0], acc[j][1]);
            *reinterpret_cast<float2*>(&S.gbuf[(row + 8) * GROW + col]) =
                make_float2(acc[j][2], acc[j][3]);
        }

        // pred computed locally from h1_cur registers
        {
            float pr[4];
            #pragma unroll
            for (int it = 0; it < 4; ++it) {
                float v = 0.0f;
                const uint32_t* qa = reinterpret_cast<const uint32_t*>(&pfA[it]);
                const uint32_t* qb = reinterpret_cast<const uint32_t*>(&pfB[it]);
                #pragma unroll
                for (int q = 0; q < 4; ++q) {
                    float2 fa = __bfloat1622float2(
                        *reinterpret_cast<const __nv_bfloat162*>(&qa[q]));
                    float2 fb = __bfloat1622float2(
                        *reinterpret_cast<const __nv_bfloat162*>(&qb[q]));
                    v += fa.x * wf0[q * 2] + fa.y * wf0[q * 2 + 1];
                    v += fb.x * wf1[q * 2] + fb.y * wf1[q * 2 + 1];
                }
                v += __shfl_down_sync(0xffffffffu, v, 8, 16);
                v += __shfl_down_sync(0xffffffffu, v, 4, 16);
                v += __shfl_down_sync(0xffffffffu, v, 2, 16);
                v += __shfl_down_sync(0xffffffffu, v, 1, 16);
                pr[it] = v;
            }
            if (kq == 0) {
                int half = lane >> 4;
                #pragma unroll
                for (int it = 0; it < 4; ++it) {
                    int m = warp * 8 + it * 2 + half;
                    S.predvS[m] = (t == 0) ? 0.0f : (pr[it] + boutv);
                }
            }
        }
        sts_h(S.hT[0], warp, lane, pfA);
        sts_h(S.hT[1], warp, lane, pfB);
        __syncthreads();   // gbuf + predvS + hT(h1) visible

        // loss (slice 0 only)
        if (s == 0 && t > 0 && tid < BC) {
            float d = __ldg(&seq[(bbase + tid) * TSTEPS + (t - 1)]) - S.predvS[tid];
            lossreg += d * d;
        }

        // layer-0 activations (pred inline) -> h0_nxt
        {
            unsigned short* h0n = &g_h0[nxt * BSZ * HID];
            float2 w_i = *reinterpret_cast<const float2*>(&S.wih0[up]);
            float2 w_f = *reinterpret_cast<const float2*>(&S.wih0[16 + up]);
            float2 w_g = *reinterpret_cast<const float2*>(&S.wih0[32 + up]);
            float2 w_o = *reinterpret_cast<const float2*>(&S.wih0[48 + up]);
            #pragma unroll
            for (int r = 0; r < 2; ++r) {
                int m = mr + r * 16;
                float pv = S.predvS[m];
                float2 gi = *reinterpret_cast<const float2*>(&S.gbuf[m * GROW + up]);
                float2 gf = *reinterpret_cast<const float2*>(&S.gbuf[m * GROW + 16 + up]);
                float2 gg = *reinterpret_cast<const float2*>(&S.gbuf[m * GROW + 32 + up]);
                float2 go = *reinterpret_cast<const float2*>(&S.gbuf[m * GROW + 48 + up]);
                float2 cv = *reinterpret_cast<const float2*>(&S.c0s[m * NU + up]);
                float cnx = sigf(gf.x + pv * w_f.x) * cv.x
                          + sigf(gi.x + pv * w_i.x) * tanha(gg.x + pv * w_g.x);
                float cny = sigf(gf.y + pv * w_f.y) * cv.y
                          + sigf(gi.y + pv * w_i.y) * tanha(gg.y + pv * w_g.y);
                float hnx = sigf(go.x + pv * w_o.x) * tanha(cnx);
                float hny = sigf(go.y + pv * w_o.y) * tanha(cny);
                *reinterpret_cast<float2*>(&S.c0s[m * NU + up]) = make_float2(cnx, cny);
                __nv_bfloat162 hb = __floats2bfloat162_rn(hnx, hny);
                *reinterpret_cast<uint32_t*>(&h0n[(bbase + m) * HID + ubase + up]) =
                    *reinterpret_cast<uint32_t*>(&hb);
            }
        }
        bar_arrive(g);   // barrier A(t): h0_nxt published

        // ===== layer-1 GEMM: h1 half chunk0 (hides barrier-A wait) =====
        #pragma unroll
        for (int j = 0; j < 4; ++j) {
            int col = wn * 32 + j * 8 + 2 * tig;
            acc[j][0] = S.bias1[col];
            acc[j][1] = S.bias1[col + 1];
            acc[j][2] = acc[j][0];
            acc[j][3] = acc[j][1];
        }
        mma_chunk(w1hb, hT0a, lane, acc);

        bar_wait(g, t * 32 + 16);
        const unsigned short* h0nv = &g_h0[nxt * BSZ * HID];
        ldg_h(h0nv,       bbase, warp, lane, pfA);
        ldg_h(h0nv + 128, bbase, warp, lane, pfB);
        mma_chunk(w1hb + 4096, hT1a, lane, acc);   // covers LDG latency
        sts_h(S.hT[0], warp, lane, pfA);           // hT0 reads all done (pre-barrier)
        __syncthreads();                            // hT1 reads done + hT0 visible
        sts_h(S.hT[1], warp, lane, pfB);
        mma_chunk(w1ib, hT0a, lane, acc);
        __syncthreads();                            // hT1 visible
        mma_chunk(w1ib + 4096, hT1a, lane, acc);
        // hT[0..1] now hold h0_cur(t+1) -> reused by next step's L0 GEMM

        // write layer-1 gates
        #pragma unroll
        for (int j = 0; j < 4; ++j) {
            int col = wn * 32 + j * 8 + 2 * tig;
            int row = wm * 16 + g8;
            *reinterpret_cast<float2*>(&S.gbuf[row * GROW + col]) =
                make_float2(acc[j][0], acc[j][1]);
            *reinterpret_cast<float2*>(&S.gbuf[(row + 8) * GROW + col]) =
                make_float2(acc[j][2], acc[j][3]);
        }
        __syncthreads();

        // layer-1 activations -> h1_nxt
        {
            unsigned short* h1n = &g_h1[nxt * BSZ * HID];
            #pragma unroll
            for (int r = 0; r < 2; ++r) {
                int m = mr + r * 16;
                float2 gi = *reinterpret_cast<const float2*>(&S.gbuf[m * GROW + up]);
                float2 gf = *reinterpret_cast<const float2*>(&S.gbuf[m * GROW + 16 + up]);
                float2 gg = *reinterpret_cast<const float2*>(&S.gbuf[m * GROW + 32 + up]);
                float2 go = *reinterpret_cast<const float2*>(&S.gbuf[m * GROW + 48 + up]);
                float2 cv = *reinterpret_cast<const float2*>(&S.c1s[m * NU + up]);
                float cnx = sigf(gf.x) * cv.x + sigf(gi.x) * tanha(gg.x);
                float cny = sigf(gf.y) * cv.y + sigf(gi.y) * tanha(gg.y);
                float hnx = sigf(go.x) * tanha(cnx);
                float hny = sigf(go.y) * tanha(cny);
                *reinterpret_cast<float2*>(&S.c1s[m * NU + up]) = make_float2(cnx, cny);
                __nv_bfloat162 hb = __floats2bfloat162_rn(hnx, hny);
                *reinterpret_cast<uint32_t*>(&h1n[(bbase + m) * HID + ubase + up]) =
                    *reinterpret_cast<uint32_t*>(&hb);
            }
        }
        bar_arrive(g);   // barrier B(t)
    }

    // ===== epilogue: final pred (from final h1, buffer 0) + loss =====
    bar_wait(g, TSTEPS * 32);
    if (s == 0) {
        ldg_h(&g_h1[0],       bbase, warp, lane, pfA);
        ldg_h(&g_h1[0] + 128, bbase, warp, lane, pfB);
        float pr[4];
        #pragma unroll
        for (int it = 0; it < 4; ++it) {
            float v = 0.0f;
            const uint32_t* qa = reinterpret_cast<const uint32_t*>(&pfA[it]);
            const uint32_t* qb = reinterpret_cast<const uint32_t*>(&pfB[it]);
            #pragma unroll
            for (int q = 0; q < 4; ++q) {
                float2 fa = __bfloat1622float2(
                    *reinterpret_cast<const __nv_bfloat162*>(&qa[q]));
                float2 fb = __bfloat1622float2(
                    *reinterpret_cast<const __nv_bfloat162*>(&qb[q]));
                v += fa.x * wf0[q * 2] + fa.y * wf0[q * 2 + 1];
                v += fb.x * wf1[q * 2] + fb.y * wf1[q * 2 + 1];
            }
            v += __shfl_down_sync(0xffffffffu, v, 8, 16);
            v += __shfl_down_sync(0xffffffffu, v, 4, 16);
            v += __shfl_down_sync(0xffffffffu, v, 2, 16);
            v += __shfl_down_sync(0xffffffffu, v, 1, 16);
            pr[it] = v;
        }
        if (kq == 0) {
            int half = lane >> 4;
            #pragma unroll
            for (int it = 0; it < 4; ++it) {
                int m = warp * 8 + it * 2 + half;
                S.predvS[m] = pr[it] + boutv;
            }
        }
        __syncthreads();
        if (tid < BC) {
            float d = __ldg(&seq[(bbase + tid) * TSTEPS + (TSTEPS - 1)]) - S.predvS[tid];
            lossreg += d * d;
            S.lossS[tid] = lossreg;
        }
        __syncthreads();
        if (tid == 0) {
            float sum = 0.0f;
            for (int i = 0; i < BC; ++i) sum += S.lossS[i];
            g_losspart[g] = sum;
        }
    }
}

__global__ void finish_kernel(float* __restrict__ out) {
    float sum = 0.0f;
    for (int i = 0; i < GBGROUPS; ++i) sum += g_losspart[i];
    out[0] = sum / (float)(BSZ * TSTEPS);
}

extern "C" void kernel_launch(void* const* d_in, const int* in_sizes, int n_in,
                              void* d_out, int out_size) {
    const float* seq  = (const float*)d_in[0];
    const float* z    = (const float*)d_in[1];
    const float* Wih0 = (const float*)d_in[3];
    const float* Whh0 = (const float*)d_in[4];
    const float* bih0 = (const float*)d_in[5];
    const float* bhh0 = (const float*)d_in[6];
    const float* Wih1 = (const float*)d_in[7];
    const float* Whh1 = (const float*)d_in[8];
    const float* bih1 = (const float*)d_in[9];
    const float* bhh1 = (const float*)d_in[10];
    const float* Wout = (const float*)d_in[11];
    const float* bout = (const float*)d_in[12];

    cudaFuncSetAttribute(lstm_kernel, cudaFuncAttributeMaxDynamicSharedMemorySize,
                         (int)sizeof(SmemLayout));

    init_kernel<<<(BSZ * HID + 255) / 256, 256>>>(z);
    lstm_kernel<<<NCTA, NTHREADS, sizeof(SmemLayout)>>>(
        seq, z, Wih0, Whh0, bih0, bhh0, Wih1, Whh1, bih1, bhh1, Wout, bout);
    finish_kernel<<<1, 1>>>((float*)d_out);
}